// round 15
// baseline (speedup 1.0000x reference)
#include <cuda_runtime.h>
#include <cstdint>
#include <math.h>

#define BB 256
#define TT 512
#define HH 256
#define EE 6
#define VV 10
#define CC 10

#define CLUSTER 8
#define NB 16            // batch columns per cluster
#define ROWS 32          // h-rows per CTA
#define THREADS 512      // 16 warps: (8 hr x 4 col) per warp, 4x4 warp grid

#define WSTRIDE 20       // floats per (kq,hr) slot row: 16 used + 4 pad (80 B, bank-clean)
#define HSTRIDE 260      // floats per Hd col: 256 used + 4 pad (1040 B, bank-clean)

typedef unsigned long long ull;

struct __align__(16) Smem {
    float W[64][32][WSTRIDE];   // [kq][hr][g*4 + (k&3)]                (163840 B)
    float Hd[2][NB][HSTRIDE];   // [buf][col][k] full h, double-buffered (33280 B)
    float Tab4[VV][ROWS][4];    // [digit][hr][gate] = (Wx@emb^T)         (5120 B)
    unsigned char dig8[NB][TT]; // all digits preloaded                   (8192 B)
};

#define FMA2(a, b, c) asm("fma.rn.f32x2 %0, %1, %2, %0;" : "+l"(a) : "l"(b), "l"(c))
#define ADD2(o, a, b) asm("add.rn.f32x2 %0, %1, %2;" : "=l"(o) : "l"(a), "l"(b))

__device__ __forceinline__ void cluster_sync_() {
    asm volatile("barrier.cluster.arrive.aligned;" ::: "memory");
    asm volatile("barrier.cluster.wait.aligned;" ::: "memory");
}

__device__ __forceinline__ float fast_sigmoid(float x) {
    return __fdividef(1.0f, 1.0f + __expf(-x));
}
__device__ __forceinline__ float fast_tanh(float x) {
    return 1.0f - __fdividef(2.0f, __expf(2.0f * x) + 1.0f);
}

__global__ void __cluster_dims__(CLUSTER, 1, 1) __launch_bounds__(THREADS, 1)
lstm_persistent_kernel(
    const int* __restrict__ x,   const float* __restrict__ emb,
    const float* __restrict__ Wxg, const float* __restrict__ Whg, const float* __restrict__ bg,
    const float* __restrict__ Wxi, const float* __restrict__ Whi, const float* __restrict__ bi,
    const float* __restrict__ Wxf, const float* __restrict__ Whf, const float* __restrict__ bf,
    const float* __restrict__ Wxo, const float* __restrict__ Who, const float* __restrict__ bo,
    const float* __restrict__ Wp,  const float* __restrict__ bp,
    float* __restrict__ out)
{
    extern __shared__ __align__(16) unsigned char smem_raw[];
    Smem& s = *reinterpret_cast<Smem*>(smem_raw);

    const int tid = threadIdx.x;
    uint32_t rank;
    asm("mov.u32 %0, %%cluster_ctarank;" : "=r"(rank));
    const int cluster = blockIdx.x / CLUSTER;
    const int colBase = cluster * NB;
    const int rowBase = (int)rank * ROWS;

    const float* WhArr[4] = {Whg, Whi, Whf, Who};
    const float* WxArr[4] = {Wxg, Wxi, Wxf, Wxo};
    const float* bArr[4]  = {bg,  bi,  bf,  bo};

    // ---------------- Prologue ----------------
    // W[k>>2][lr][gate*4 + (k&3)] = Wh_gate[rowBase+lr][k]
    for (int idx = tid; idx < 4 * ROWS * HH; idx += THREADS) {
        const int k    = idx & 255;
        const int lr   = (idx >> 8) & 31;
        const int gate = idx >> 13;
        s.W[k >> 2][lr][gate * 4 + (k & 3)] =
            WhArr[gate][(size_t)(rowBase + lr) * HH + k];
    }
    // Tab4[d][lr][g] = (Wx_gate @ emb^T)[rowBase+lr][d]
    for (int idx = tid; idx < VV * ROWS * 4; idx += THREADS) {
        const int g  = idx & 3;
        const int lr = (idx >> 2) & 31;
        const int d  = idx / (ROWS * 4);
        const float* wx = WxArr[g] + (size_t)(rowBase + lr) * EE;
        float acc = 0.0f;
        #pragma unroll
        for (int e = 0; e < EE; e++) acc += wx[e] * emb[d * EE + e];
        s.Tab4[d][lr][g] = acc;
    }
    // Zero h (both buffers incl. padding)
    for (int i = tid; i < 2 * NB * HSTRIDE; i += THREADS)
        reinterpret_cast<float*>(s.Hd)[i] = 0.0f;
    // Preload ALL digits as u8
    for (int i = tid; i < NB * TT; i += THREADS) {
        const int col = i >> 9, t = i & (TT - 1);
        s.dig8[col][t] = (unsigned char)x[(size_t)(colBase + col) * TT + t];
    }

    // Thread coordinates: warp = 8 hr x 4 col
    const int hr  = ((tid >> 7) << 3) | ((tid >> 2) & 7);   // 0..31
    const int col = (((tid >> 5) & 3) << 2) | (tid & 3);    // 0..15

    // Bias in registers: reference (H,B)+(H,) broadcasts over trailing batch
    // axis (H==B) -> bias indexed by BATCH column.
    float bsr[4];
    #pragma unroll
    for (int g = 0; g < 4; g++) bsr[g] = bArr[g][colBase + col];

    __syncthreads();
    cluster_sync_();   // peers' Hd zeroed before any remote h writes

    // DSMEM bases (mapa once)
    uint32_t rbase[CLUSTER];
    {
        uint32_t l0 = (uint32_t)__cvta_generic_to_shared(&s.Hd[0][0][0]);
        #pragma unroll
        for (int r = 0; r < CLUSTER; r++)
            asm("mapa.shared::cluster.u32 %0, %1, %2;" : "=r"(rbase[r]) : "r"(l0), "r"(r));
    }
    const uint32_t hOff0 = (uint32_t)((col * HSTRIDE + rowBase + hr) * 4);
    const uint32_t bufStride = NB * HSTRIDE * 4;

    float cstate = 0.0f;
    int cur = 0;

    const float* __restrict__ wrow = &s.W[0][hr][0];

    for (int t = 0; t < TT; t++) {
        ull aG0 = 0, aG1 = 0, aI0 = 0, aI1 = 0,
            aF0 = 0, aF1 = 0, aO0 = 0, aO1 = 0;

        const float* __restrict__ hcol = &s.Hd[cur][col][0];

        #pragma unroll 4
        for (int kq = 0; kq < 64; kq++) {
            const float* wk = wrow + kq * (32 * WSTRIDE);
            const ulonglong2 h4 = *reinterpret_cast<const ulonglong2*>(hcol + kq * 4);
            const ulonglong2 wg = *reinterpret_cast<const ulonglong2*>(wk + 0);
            const ulonglong2 wi = *reinterpret_cast<const ulonglong2*>(wk + 4);
            const ulonglong2 wf = *reinterpret_cast<const ulonglong2*>(wk + 8);
            const ulonglong2 wo = *reinterpret_cast<const ulonglong2*>(wk + 12);
            FMA2(aG0, wg.x, h4.x); FMA2(aG1, wg.y, h4.y);
            FMA2(aI0, wi.x, h4.x); FMA2(aI1, wi.y, h4.y);
            FMA2(aF0, wf.x, h4.x); FMA2(aF1, wf.y, h4.y);
            FMA2(aO0, wo.x, h4.x); FMA2(aO1, wo.y, h4.y);
        }

        // ---- fused epilogue (all in registers) ----
        const int d = s.dig8[col][t];
        const float4 tab = *reinterpret_cast<const float4*>(&s.Tab4[d][hr][0]);

        ull sG, sI, sF, sO;
        ADD2(sG, aG0, aG1); ADD2(sI, aI0, aI1);
        ADD2(sF, aF0, aF1); ADD2(sO, aO0, aO1);
        const float2 pG = *reinterpret_cast<const float2*>(&sG);
        const float2 pI = *reinterpret_cast<const float2*>(&sI);
        const float2 pF = *reinterpret_cast<const float2*>(&sF);
        const float2 pO = *reinterpret_cast<const float2*>(&sO);

        const float gg = fast_tanh  (pG.x + pG.y + tab.x + bsr[0]);
        const float ii = fast_sigmoid(pI.x + pI.y + tab.y + bsr[1]);
        const float ff = fast_sigmoid(pF.x + pF.y + tab.z + bsr[2]);
        const float oo = fast_sigmoid(pO.x + pO.y + tab.w + bsr[3]);
        cstate = gg * ii + cstate * ff;
        const float hh = fast_tanh(cstate) * oo;

        // broadcast h to all 8 CTAs (double-buffered -> race-free, 1 barrier/step)
        const uint32_t off = hOff0 + (uint32_t)(cur ^ 1) * bufStride;
        #pragma unroll
        for (int r = 0; r < CLUSTER; r++) {
            asm volatile("st.shared::cluster.f32 [%0], %1;"
                         :: "r"(rbase[r] + off), "f"(hh) : "memory");
        }

        cluster_sync_();   // remote h visible cluster-wide; also orders local reads
        cur ^= 1;
    }

    // -------- Final projection: out[b][j] = Wp[j,:] . h[:,b] + bp[j] --------
    if (tid < NB * CC) {
        const int pc = tid / CC;
        const int j  = tid % CC;
        float acc = bp[j];
        const float* wp = Wp + (size_t)j * HH;
        const float* hc = &s.Hd[cur][pc][0];
        #pragma unroll 4
        for (int r = 0; r < HH; r++)
            acc = fmaf(wp[r], hc[r], acc);
        out[(size_t)(colBase + pc) * CC + j] = acc;
    }
}

extern "C" void kernel_launch(void* const* d_in, const int* in_sizes, int n_in,
                              void* d_out, int out_size) {
    const int*   x   = (const int*)  d_in[0];
    const float* emb = (const float*)d_in[1];
    const float* Wxg = (const float*)d_in[2];
    const float* Whg = (const float*)d_in[3];
    const float* bg  = (const float*)d_in[4];
    const float* Wxi = (const float*)d_in[5];
    const float* Whi = (const float*)d_in[6];
    const float* bi  = (const float*)d_in[7];
    const float* Wxf = (const float*)d_in[8];
    const float* Whf = (const float*)d_in[9];
    const float* bf  = (const float*)d_in[10];
    const float* Wxo = (const float*)d_in[11];
    const float* Who = (const float*)d_in[12];
    const float* bo  = (const float*)d_in[13];
    const float* Wp  = (const float*)d_in[14];
    const float* bp  = (const float*)d_in[15];
    float* out = (float*)d_out;

    cudaFuncSetAttribute(lstm_persistent_kernel,
                         cudaFuncAttributeMaxDynamicSharedMemorySize,
                         (int)sizeof(Smem));

    lstm_persistent_kernel<<<128, THREADS, sizeof(Smem)>>>(
        x, emb, Wxg, Whg, bg, Wxi, Whi, bi, Wxf, Whf, bf, Wxo, Who, bo, Wp, bp, out);
}